// round 15
// baseline (speedup 1.0000x reference)
#include <cuda_runtime.h>
#include <math.h>
#include <stdint.h>

#define BATCH 256
#define SIGLEN 2048
#define L1P 1022
#define L2P 339
#define L3P 168
#define C1 128
#define C2 64
#define C3 64
#define FCIN 10752
#define EPS_BN 1e-5f

typedef unsigned long long ull;

// ---- scratch ----
__device__ float g_h1T[BATCH * L1P * C1];   // [b][pos][ic]
__device__ float g_h2T[BATCH * L2P * C2];   // [b][pos][oc]
__device__ float g_h3T[FCIN * BATCH];       // [feature][batch]
__device__ float g_w2T[5 * 64 * 128];       // [k][oc][ic]
__device__ float g_w3T[3 * 64 * 64];        // [k][oc][ic]
__device__ float g_part[256 * BATCH * 48];
__device__ float g_theta[BATCH * 5];

__device__ __forceinline__ void fma2(ull& d, ull a, ull b) {
    asm("fma.rn.f32x2 %0, %1, %2, %0;" : "+l"(d) : "l"(a), "l"(b));
}
__device__ __forceinline__ ull dup2(float v) {
    ull r; asm("mov.b64 %0, {%1, %1};" : "=l"(r) : "f"(v)); return r;
}
__device__ __forceinline__ float lo32(ull v) { return __uint_as_float((unsigned)v); }
__device__ __forceinline__ float hi32(ull v) { return __uint_as_float((unsigned)(v >> 32)); }
__device__ __forceinline__ unsigned ulo(ull v) { return (unsigned)v; }
__device__ __forceinline__ unsigned uhi(ull v) { return (unsigned)(v >> 32); }

__device__ __forceinline__ void cpa16(void* dst, const void* src) {
    unsigned d = (unsigned)__cvta_generic_to_shared(dst);
    asm volatile("cp.async.cg.shared.global [%0], [%1], 16;" :: "r"(d), "l"(src));
}
#define CP_COMMIT()  asm volatile("cp.async.commit_group;" ::: "memory")
#define CP_WAIT0()   asm volatile("cp.async.wait_group 0;" ::: "memory")

__device__ __forceinline__ float f2tf_f(float v) {
    unsigned r; asm("cvt.rna.tf32.f32 %0, %1;" : "=r"(r) : "f"(v));
    return __uint_as_float(r);
}
// (hi = rounded tf32, lo = raw residual; HMMA truncates lo's tail itself)
__device__ __forceinline__ float2 tfs2(float v) {
    float hf = f2tf_f(v);
    return make_float2(hf, v - hf);
}
__device__ __forceinline__ void mma_tf32(float* d,
        unsigned a0, unsigned a1, unsigned a2, unsigned a3,
        unsigned b0, unsigned b1) {
    asm("mma.sync.aligned.m16n8k8.row.col.f32.tf32.tf32.f32 "
        "{%0,%1,%2,%3}, {%4,%5,%6,%7}, {%8,%9}, {%0,%1,%2,%3};"
        : "+f"(d[0]), "+f"(d[1]), "+f"(d[2]), "+f"(d[3])
        : "r"(a0), "r"(a1), "r"(a2), "r"(a3), "r"(b0), "r"(b1));
}

// ============================================================
// Kernel 0: weight transposes
// ============================================================
__global__ void k_prep(const float* __restrict__ w2, const float* __restrict__ w3) {
    int i = blockIdx.x * blockDim.x + threadIdx.x;
    if (i < 5 * 64 * 128) {
        int k = i >> 13, oc = (i >> 7) & 63, ic = i & 127;
        g_w2T[i] = w2[oc * 640 + ic * 5 + k];
    }
    if (i < 3 * 64 * 64) {
        int k = i >> 12, oc = (i >> 6) & 63, ic = i & 63;
        g_w3T[i] = w3[oc * 192 + ic * 3 + k];
    }
}

// ============================================================
// Kernel 1: conv1 (3->128, k3) + BN + pool(3,2) + relu -> g_h1T
// ============================================================
__global__ void __launch_bounds__(128) k_conv1(
        const float* __restrict__ x,
        const float* __restrict__ w,
        const float* __restrict__ bias,
        const float* __restrict__ bng,
        const float* __restrict__ bnb,
        const float* __restrict__ bnm,
        const float* __restrict__ bnv) {
    const int b  = blockIdx.y;
    const int p0 = blockIdx.x * 64;
    const int oc = threadIdx.x;
    __shared__ float2 xs2[3][132];
    __shared__ float outS[64][128];

    const int t0 = 2 * p0;
    for (int idx = threadIdx.x; idx < 3 * 131; idx += 128) {
        int ch = idx / 131, j = idx % 131;
        int t = t0 + j;
        const float* xc = x + (b * 3 + ch) * SIGLEN;
        float v0 = (t < SIGLEN) ? xc[t] : 0.f;
        float v1 = (t + 1 < SIGLEN) ? xc[t + 1] : 0.f;
        xs2[ch][j] = make_float2(v0, v1);
    }
    ull wd[9];
#pragma unroll
    for (int j = 0; j < 9; ++j) wd[j] = dup2(w[oc * 9 + j]);
    float scale = bng[oc] / sqrtf(bnv[oc] + EPS_BN);
    float shift = bnb[oc] + (bias[oc] - bnm[oc]) * scale;
    __syncthreads();

    auto cpair = [&](int i) {
        ull a0 = 0ull, a1 = 0ull, a2 = 0ull;
#pragma unroll
        for (int k = 0; k < 3; ++k) {
            fma2(a0, wd[k],     *(const ull*)&xs2[0][2 * i + k]);
            fma2(a1, wd[3 + k], *(const ull*)&xs2[1][2 * i + k]);
            fma2(a2, wd[6 + k], *(const ull*)&xs2[2][2 * i + k]);
        }
        float lo = lo32(a0) + lo32(a1) + lo32(a2);
        float hi = hi32(a0) + hi32(a1) + hi32(a2);
        return make_float2(lo, hi);
    };

    float2 prev = cpair(0);
#pragma unroll 4
    for (int pl = 0; pl < 64; ++pl) {
        float2 nxt = cpair(pl + 1);
        float y0 = fmaf(prev.x, scale, shift);
        float y1 = fmaf(prev.y, scale, shift);
        float y2 = fmaf(nxt.x,  scale, shift);
        outS[pl][oc] = fmaxf(fmaxf(fmaxf(y0, y1), y2), 0.f);
        prev = nxt;
    }
    __syncthreads();
    for (int idx = threadIdx.x; idx < 64 * 32; idx += 128) {
        int pl = idx >> 5, q = idx & 31;
        int p = p0 + pl;
        if (p < L1P)
            *(float4*)&g_h1T[(b * L1P + p) * C1 + q * 4] =
                *(const float4*)&outS[pl][q * 4];
    }
}

// ============================================================
// Kernel 2: conv2 tf32 3x-split, PRE-SPLIT smem (float2 hi/lo)  [HOT]
// 512 threads (16 warps): mw 0..7 (m16), nw 0..1 (n32).
// Mainloop per ks: 12 LDS.64 + 12 HMMA, no ALU splits.
// W[k+1] prefetched into regs during mainloop. grid (9, 256).
// ============================================================
#define CV2_SMEM ((132 * 132 * 2 + 64 * 132 * 2 + 128) * 4)   // 207,488 B

__global__ void __launch_bounds__(512, 1) k_conv2mma(
        const float* __restrict__ bias,
        const float* __restrict__ bng,
        const float* __restrict__ bnb,
        const float* __restrict__ bnm,
        const float* __restrict__ bnv) {
    extern __shared__ float2 sm2[];
    float2* X2 = sm2;                       // [132][132] (hi,lo)
    float2* W2 = sm2 + 132 * 132;           // [64][132]
    float*  scS = (float*)(sm2 + 132 * 132 + 64 * 132);
    float*  shS = scS + 64;

    const int b    = blockIdx.y;
    const int bx   = blockIdx.x;
    const int ct0  = bx * 126;
    const int tid  = threadIdx.x;
    const int lane = tid & 31;
    const int wid  = tid >> 5;
    const int mw   = wid & 7;       // m16 group
    const int nw   = wid >> 3;      // n32 group

    if (tid < 64) {
        float sc = bng[tid] * rsqrtf(bnv[tid] + EPS_BN);
        scS[tid] = sc;
        shS[tid] = bnb[tid] + (bias[tid] - bnm[tid]) * sc;
    }

    // ---- X fill: LDG f32 -> split -> STS float2 ----
    const float* h1b = &g_h1T[(size_t)b * L1P * C1];
    for (int idx = tid; idx < 132 * 32; idx += 512) {
        int j = idx >> 5, icq = idx & 31;
        int t = ct0 + j;
        float4 v = (t < L1P) ? *(const float4*)(h1b + (size_t)t * C1 + icq * 4)
                             : make_float4(0.f, 0.f, 0.f, 0.f);
        float2* dst = X2 + j * 132 + icq * 4;
        dst[0] = tfs2(v.x); dst[1] = tfs2(v.y);
        dst[2] = tfs2(v.z); dst[3] = tfs2(v.w);
    }

    // ---- W prefetch machinery (16 floats / thread) ----
    float4 wr[4];
    auto ldW = [&](int k) {
#pragma unroll
        for (int i = 0; i < 4; ++i) {
            int q = tid + i * 512;          // 0..2047 quads
            wr[i] = *(const float4*)(g_w2T + k * 8192 + q * 4);
        }
    };
    auto stW = [&]() {
#pragma unroll
        for (int i = 0; i < 4; ++i) {
            int q = tid + i * 512;
            int row = q >> 5, icq = q & 31;
            float2* dst = W2 + row * 132 + icq * 4;
            dst[0] = tfs2(wr[i].x); dst[1] = tfs2(wr[i].y);
            dst[2] = tfs2(wr[i].z); dst[3] = tfs2(wr[i].w);
        }
    };
    ldW(0); stW();
    __syncthreads();

    float c[4][4];
#pragma unroll
    for (int j = 0; j < 4; ++j)
#pragma unroll
        for (int q = 0; q < 4; ++q) c[j][q] = 0.f;

    for (int k = 0; k < 5; ++k) {
        if (k < 4) ldW(k + 1);
        const float2* xp = X2 + (mw * 16 + (lane >> 2) + k) * 132 + (lane & 3);
        const float2* wp = W2 + (nw * 32 + (lane >> 2)) * 132 + (lane & 3);
#pragma unroll 4
        for (int ks = 0; ks < 16; ++ks) {
            const int kb = ks * 8;
            ull a0 = *(const ull*)&xp[kb];
            ull a1 = *(const ull*)&xp[kb + 8 * 132];
            ull a2 = *(const ull*)&xp[kb + 4];
            ull a3 = *(const ull*)&xp[kb + 8 * 132 + 4];
            ull b0[4], b1[4];
#pragma unroll
            for (int j = 0; j < 4; ++j) {
                b0[j] = *(const ull*)&wp[j * 8 * 132 + kb];
                b1[j] = *(const ull*)&wp[j * 8 * 132 + kb + 4];
            }
#pragma unroll
            for (int j = 0; j < 4; ++j) {
                mma_tf32(c[j], ulo(a0), ulo(a1), ulo(a2), ulo(a3),
                         ulo(b0[j]), ulo(b1[j]));
                mma_tf32(c[j], uhi(a0), uhi(a1), uhi(a2), uhi(a3),
                         ulo(b0[j]), ulo(b1[j]));
                mma_tf32(c[j], ulo(a0), ulo(a1), ulo(a2), ulo(a3),
                         uhi(b0[j]), uhi(b1[j]));
            }
        }
        __syncthreads();
        if (k < 4) { stW(); __syncthreads(); }
    }

    // ---- epilogue ----
    float* convS = (float*)sm2;    // [128][68]
#pragma unroll
    for (int j = 0; j < 4; ++j) {
        int row = mw * 16 + (lane >> 2);
        int col = nw * 32 + j * 8 + 2 * (lane & 3);
        convS[row * 68 + col]           = c[j][0];
        convS[row * 68 + col + 1]       = c[j][1];
        convS[(row + 8) * 68 + col]     = c[j][2];
        convS[(row + 8) * 68 + col + 1] = c[j][3];
    }
    __syncthreads();
    for (int idx = tid; idx < 42 * 64; idx += 512) {
        int oc = idx & 63, pl = idx >> 6;
        int p = bx * 42 + pl;
        if (p < L2P) {
            float sc = scS[oc], sh = shS[oc];
            float y0 = fmaf(convS[(3 * pl) * 68 + oc],     sc, sh);
            float y1 = fmaf(convS[(3 * pl + 1) * 68 + oc], sc, sh);
            float y2 = fmaf(convS[(3 * pl + 2) * 68 + oc], sc, sh);
            g_h2T[(b * L2P + p) * C2 + oc] = fmaxf(fmaxf(fmaxf(y0, y1), y2), 0.f);
        }
    }
}

// ============================================================
// Kernel 3: conv3 tf32 3x-split, PRE-SPLIT smem, 512 threads.
// All 3 W taps resident. grid (3, 256).
// ============================================================
#define CV3_SMEM ((131 * 68 * 2 + 192 * 68 * 2 + 128) * 4)   // 176,224 B

__global__ void __launch_bounds__(512, 1) k_conv3mma(
        const float* __restrict__ bias,
        const float* __restrict__ bng,
        const float* __restrict__ bnb,
        const float* __restrict__ bnm,
        const float* __restrict__ bnv) {
    extern __shared__ float2 sm2[];
    float2* X2 = sm2;                       // [131][68]
    float2* W2 = sm2 + 131 * 68;            // [192][68]
    float*  scS = (float*)(sm2 + 131 * 68 + 192 * 68);
    float*  shS = scS + 64;

    const int b    = blockIdx.y;
    const int bx   = blockIdx.x;
    const int ct0  = bx * 126;
    const int tid  = threadIdx.x;
    const int lane = tid & 31;
    const int wid  = tid >> 5;
    const int mw   = wid & 7;
    const int nw   = wid >> 3;

    if (tid < 64) {
        float sc = bng[tid] * rsqrtf(bnv[tid] + EPS_BN);
        scS[tid] = sc;
        shS[tid] = bnb[tid] + (bias[tid] - bnm[tid]) * sc;
    }

    for (int idx = tid; idx < 131 * 16; idx += 512) {
        int j = idx >> 4, icq = idx & 15;
        int t = ct0 + j;
        float4 v = (t < L2P)
            ? *(const float4*)&g_h2T[(b * L2P + t) * C2 + icq * 4]
            : make_float4(0.f, 0.f, 0.f, 0.f);
        float2* dst = X2 + j * 68 + icq * 4;
        dst[0] = tfs2(v.x); dst[1] = tfs2(v.y);
        dst[2] = tfs2(v.z); dst[3] = tfs2(v.w);
    }
    for (int idx = tid; idx < 192 * 16; idx += 512) {
        int row = idx >> 4, icq = idx & 15;
        float4 v = *(const float4*)(g_w3T + row * 64 + icq * 4);
        float2* dst = W2 + row * 68 + icq * 4;
        dst[0] = tfs2(v.x); dst[1] = tfs2(v.y);
        dst[2] = tfs2(v.z); dst[3] = tfs2(v.w);
    }
    __syncthreads();

    float c[4][4];
#pragma unroll
    for (int j = 0; j < 4; ++j)
#pragma unroll
        for (int q = 0; q < 4; ++q) c[j][q] = 0.f;

#pragma unroll
    for (int k = 0; k < 3; ++k) {
        const float2* xp = X2 + (mw * 16 + (lane >> 2) + k) * 68 + (lane & 3);
        const float2* wp = W2 + (k * 64 + nw * 32 + (lane >> 2)) * 68 + (lane & 3);
#pragma unroll 4
        for (int ks = 0; ks < 8; ++ks) {
            const int kb = ks * 8;
            ull a0 = *(const ull*)&xp[kb];
            ull a1 = *(const ull*)&xp[kb + 8 * 68];
            ull a2 = *(const ull*)&xp[kb + 4];
            ull a3 = *(const ull*)&xp[kb + 8 * 68 + 4];
            ull b0[4], b1[4];
#pragma unroll
            for (int j = 0; j < 4; ++j) {
                b0[j] = *(const ull*)&wp[j * 8 * 68 + kb];
                b1[j] = *(const ull*)&wp[j * 8 * 68 + kb + 4];
            }
#pragma unroll
            for (int j = 0; j < 4; ++j) {
                mma_tf32(c[j], ulo(a0), ulo(a1), ulo(a2), ulo(a3),
                         ulo(b0[j]), ulo(b1[j]));
                mma_tf32(c[j], uhi(a0), uhi(a1), uhi(a2), uhi(a3),
                         ulo(b0[j]), ulo(b1[j]));
                mma_tf32(c[j], ulo(a0), ulo(a1), ulo(a2), ulo(a3),
                         uhi(b0[j]), uhi(b1[j]));
            }
        }
    }
    __syncthreads();

    float* convS = (float*)sm2;    // [128][68]
#pragma unroll
    for (int j = 0; j < 4; ++j) {
        int row = mw * 16 + (lane >> 2);
        int col = nw * 32 + j * 8 + 2 * (lane & 3);
        convS[row * 68 + col]           = c[j][0];
        convS[row * 68 + col + 1]       = c[j][1];
        convS[(row + 8) * 68 + col]     = c[j][2];
        convS[(row + 8) * 68 + col + 1] = c[j][3];
    }
    __syncthreads();
    for (int idx = tid; idx < 63 * 64; idx += 512) {
        int oc = idx & 63, pl = idx >> 6;
        int p = bx * 63 + pl;
        if (p < L3P) {
            float sc = scS[oc], sh = shS[oc];
            float y0 = fmaf(convS[(2 * pl) * 68 + oc],     sc, sh);
            float y1 = fmaf(convS[(2 * pl + 1) * 68 + oc], sc, sh);
            float y2 = fmaf(convS[(2 * pl + 2) * 68 + oc], sc, sh);
            float y = fmaxf(fmaxf(fmaxf(y0, y1), y2), 0.f);
            g_h3T[(oc * L3P + p) * BATCH + b] = y;
        }
    }
}

// ============================================================
// Kernel 4a: fc1 split-K, x-slab staged in smem.
// ============================================================
#define FCA_SMEM ((2016 + 10752) * 4)   // 51,072 B

__global__ void __launch_bounds__(256) k_fcA(const float* __restrict__ fc1w) {
    extern __shared__ float sm[];
    float* wsS = sm;           // [42][48]
    float* xS  = sm + 2016;    // [42][256]

    const int chunk = blockIdx.x;
    const int r = threadIdx.x;

    for (int idx = r; idx < 42 * 48; idx += 256) {
        int o = idx / 42, k = idx % 42;
        wsS[k * 48 + o] = fc1w[o * FCIN + chunk * 42 + k];
    }
    for (int i = r * 4; i < 10752; i += 1024)
        cpa16(xS + i, g_h3T + (size_t)chunk * 10752 + i);
    CP_COMMIT(); CP_WAIT0();
    __syncthreads();

    ull acc[24];
#pragma unroll
    for (int p = 0; p < 24; ++p) acc[p] = 0ull;

#pragma unroll 2
    for (int k = 0; k < 42; ++k) {
        ull xd = dup2(xS[k * 256 + r]);
#pragma unroll
        for (int p = 0; p < 24; ++p)
            fma2(acc[p], *(const ull*)&wsS[k * 48 + 2 * p], xd);
    }
    float* outp = &g_part[(chunk * BATCH + r) * 48];
#pragma unroll
    for (int p = 0; p < 24; ++p) {
        outp[2 * p]     = lo32(acc[p]);
        outp[2 * p + 1] = hi32(acc[p]);
    }
}

// ============================================================
// Kernel 4b: reduce (parallelized) + fc2/fc3/fc4 + tanh
// ============================================================
__global__ void __launch_bounds__(256) k_fcB(
        const float* __restrict__ fc1b,
        const float* __restrict__ fc2w, const float* __restrict__ fc2b,
        const float* __restrict__ fc3w, const float* __restrict__ fc3b,
        const float* __restrict__ fc4w, const float* __restrict__ fc4b) {
    const int r = blockIdx.x;
    const int tid = threadIdx.x;
    const int t = tid % 48, g = tid / 48;
    __shared__ float part[5][48];
    __shared__ float s1[48], s2[32], s3[16];

    if (g < 5) {
        int c0 = g * 52;
        int c1 = (c0 + 52 < 256) ? c0 + 52 : 256;
        float a = 0.f;
        for (int c = c0; c < c1; ++c)
            a += g_part[(c * BATCH + r) * 48 + t];
        part[g][t] = a;
    }
    __syncthreads();
    if (tid < 48) {
        float a = part[0][tid] + part[1][tid] + part[2][tid]
                + part[3][tid] + part[4][tid];
        s1[tid] = fmaxf(a + fc1b[tid], 0.f);
    }
    __syncthreads();
    if (tid < 32) {
        float a2 = 0.f;
#pragma unroll
        for (int k = 0; k < 48; ++k) a2 = fmaf(s1[k], fc2w[tid * 48 + k], a2);
        s2[tid] = fmaxf(a2 + fc2b[tid], 0.f);
    }
    __syncthreads();
    if (tid < 16) {
        float a3 = 0.f;
#pragma unroll
        for (int k = 0; k < 32; ++k) a3 = fmaf(s2[k], fc3w[tid * 32 + k], a3);
        s3[tid] = fmaxf(a3 + fc3b[tid], 0.f);
    }
    __syncthreads();
    if (tid < 5) {
        float a4 = 0.f;
#pragma unroll
        for (int k = 0; k < 16; ++k) a4 = fmaf(s3[k], fc4w[tid * 16 + k], a4);
        g_theta[r * 5 + tid] = tanhf(a4 + fc4b[tid]);
    }
}

// ============================================================
// Kernel 5: CPAB integrate + resample
// ============================================================
__global__ void k_warp(const float* __restrict__ x,
                       const float* __restrict__ basis,
                       float* __restrict__ out) {
    const int b   = blockIdx.x;
    const int tid = threadIdx.x;
    __shared__ float sa[6], sb[6];
    if (tid < 12) {
        float a = 0.f;
#pragma unroll
        for (int k = 0; k < 5; ++k)
            a = fmaf(g_theta[b * 5 + k], basis[tid * 5 + k], a);
        if (tid & 1) sb[tid >> 1] = a; else sa[tid >> 1] = a;
    }
    __syncthreads();
    float la[6], lb[6];
#pragma unroll
    for (int c = 0; c < 6; ++c) { la[c] = sa[c]; lb[c] = sb[c]; }
    const float INF = __int_as_float(0x7f800000);

    for (int r = 0; r < 8; ++r) {
        int i = tid + r * 256;
        float xv = (float)i / 2047.0f;
        float t = 1.0f;
#pragma unroll 1
        for (int it = 0; it < 7; ++it) {
            int c = (int)floorf(xv * 6.0f);
            c = c < 0 ? 0 : (c > 5 ? 5 : c);
            float a  = la[c];
            float bc = lb[c];
            float v  = fmaf(a, xv, bc);
            float xb = (v >= 0.f) ? (float)(c + 1) / 6.0f : (float)c / 6.0f;
            bool  big = fabsf(a) > 1e-8f;
            float a_s = big ? a : 1.0f;
            float boa = bc / a_s;
            float z   = xv + boa;
            float zb  = xb + boa;
            float zden  = (fabsf(z) > 1e-12f) ? z : 1e-12f;
            float ratio = zb / zden;
            float t_exp = logf(fmaxf(ratio, 1e-12f)) / a_s;
            float v_s   = (fabsf(v) > 1e-12f) ? v : 1.0f;
            float t_lin = (xb - xv) / v_s;
            float thit  = big ? t_exp : t_lin;
            bool valid = (fabsf(v) > 1e-12f) && (thit > 0.f) &&
                         ((big ? ratio : 1.0f) > 0.f);
            thit = valid ? thit : INF;
            float tau = fminf(t, thit);
            float x_new = big ? (z * expf(a * tau) - (z - xv))
                              : fmaf(bc, tau, xv);
            bool hit = (thit <= t);
            float nudge = (v >= 0.f) ? 1e-6f : -1e-6f;
            xv = hit ? (xb + nudge) : x_new;
            xv = fminf(fmaxf(xv, 0.f), 1.f);
            t = fmaxf(t - tau, 0.f);
        }
        float p = fminf(fmaxf(xv, 0.f), 1.f) * 2047.0f;
        int x0 = (int)floorf(p);
        x0 = x0 < 0 ? 0 : (x0 > 2046 ? 2046 : x0);
        float wgt = p - (float)x0;
#pragma unroll
        for (int ch = 0; ch < 3; ++ch) {
            float d0 = x[(b * 3 + ch) * SIGLEN + x0];
            float d1 = x[(b * 3 + ch) * SIGLEN + x0 + 1];
            out[(b * 3 + ch) * SIGLEN + i] = d0 * (1.0f - wgt) + d1 * wgt;
        }
    }
}

// ============================================================
extern "C" void kernel_launch(void* const* d_in, const int* in_sizes, int n_in,
                              void* d_out, int out_size) {
    const float* x     = (const float*)d_in[0];
    const float* c1w   = (const float*)d_in[1];
    const float* c1b   = (const float*)d_in[2];
    const float* bn1g  = (const float*)d_in[3];
    const float* bn1b  = (const float*)d_in[4];
    const float* bn1m  = (const float*)d_in[5];
    const float* bn1v  = (const float*)d_in[6];
    const float* c2w   = (const float*)d_in[7];
    const float* c2b   = (const float*)d_in[8];
    const float* bn2g  = (const float*)d_in[9];
    const float* bn2b  = (const float*)d_in[10];
    const float* bn2m  = (const float*)d_in[11];
    const float* bn2v  = (const float*)d_in[12];
    const float* c3w   = (const float*)d_in[13];
    const float* c3b   = (const float*)d_in[14];
    const float* bn3g  = (const float*)d_in[15];
    const float* bn3b  = (const float*)d_in[16];
    const float* bn3m  = (const float*)d_in[17];
    const float* bn3v  = (const float*)d_in[18];
    const float* fc1w  = (const float*)d_in[19];
    const float* fc1b  = (const float*)d_in[20];
    const float* fc2w  = (const float*)d_in[21];
    const float* fc2b  = (const float*)d_in[22];
    const float* fc3w  = (const float*)d_in[23];
    const float* fc3b  = (const float*)d_in[24];
    const float* fc4w  = (const float*)d_in[25];
    const float* fc4b  = (const float*)d_in[26];
    const float* basis = (const float*)d_in[27];
    float* out = (float*)d_out;

    static int attr_done = 0;
    if (!attr_done) {
        cudaFuncSetAttribute(k_conv2mma,
                             cudaFuncAttributeMaxDynamicSharedMemorySize, CV2_SMEM);
        cudaFuncSetAttribute(k_conv3mma,
                             cudaFuncAttributeMaxDynamicSharedMemorySize, CV3_SMEM);
        cudaFuncSetAttribute(k_fcA,
                             cudaFuncAttributeMaxDynamicSharedMemorySize, FCA_SMEM);
        attr_done = 1;
    }

    k_prep<<<160, 256>>>(c2w, c3w);
    dim3 g1(16, BATCH);  k_conv1<<<g1, 128>>>(x, c1w, c1b, bn1g, bn1b, bn1m, bn1v);
    dim3 g2(9,  BATCH);  k_conv2mma<<<g2, 512, CV2_SMEM>>>(c2b, bn2g, bn2b, bn2m, bn2v);
    dim3 g3(3,  BATCH);  k_conv3mma<<<g3, 512, CV3_SMEM>>>(c3b, bn3g, bn3b, bn3m, bn3v);
    k_fcA<<<256, 256, FCA_SMEM>>>(fc1w);
    k_fcB<<<BATCH, 256>>>(fc1b, fc2w, fc2b, fc3w, fc3b, fc4w, fc4b);
    k_warp<<<BATCH, 256>>>(x, basis, out);
}

// round 16
// speedup vs baseline: 1.3010x; 1.3010x over previous
#include <cuda_runtime.h>
#include <math.h>
#include <stdint.h>

#define BATCH 256
#define SIGLEN 2048
#define L1P 1022
#define L2P 339
#define L3P 168
#define C1 128
#define C2 64
#define C3 64
#define FCIN 10752
#define EPS_BN 1e-5f

typedef unsigned long long ull;

// ---- scratch ----
__device__ float g_h1T[BATCH * L1P * C1];   // [b][pos][ic]
__device__ float g_h2T[BATCH * L2P * C2];   // [b][pos][oc]
__device__ float g_h3T[FCIN * BATCH];       // [feature][batch]
__device__ float g_w2T[5 * 64 * 128];       // [k][oc][ic]
__device__ float g_w3T[3 * 64 * 64];        // [k][oc][ic]
__device__ float g_part[256 * BATCH * 48];
__device__ float g_theta[BATCH * 5];

__device__ __forceinline__ void fma2(ull& d, ull a, ull b) {
    asm("fma.rn.f32x2 %0, %1, %2, %0;" : "+l"(d) : "l"(a), "l"(b));
}
__device__ __forceinline__ ull dup2(float v) {
    ull r; asm("mov.b64 %0, {%1, %1};" : "=l"(r) : "f"(v)); return r;
}
__device__ __forceinline__ float lo32(ull v) { return __uint_as_float((unsigned)v); }
__device__ __forceinline__ float hi32(ull v) { return __uint_as_float((unsigned)(v >> 32)); }

__device__ __forceinline__ void cpa16(void* dst, const void* src) {
    unsigned d = (unsigned)__cvta_generic_to_shared(dst);
    asm volatile("cp.async.cg.shared.global [%0], [%1], 16;" :: "r"(d), "l"(src));
}
#define CP_COMMIT()  asm volatile("cp.async.commit_group;" ::: "memory")
#define CP_WAIT0()   asm volatile("cp.async.wait_group 0;" ::: "memory")

__device__ __forceinline__ float f2tf_f(float v) {
    unsigned r; asm("cvt.rna.tf32.f32 %0, %1;" : "=r"(r) : "f"(v));
    return __uint_as_float(r);
}
// hi: rounded tf32; lo: raw f32 residual (HMMA truncates low bits itself)
__device__ __forceinline__ void tfsplit(float v, unsigned& h, unsigned& l) {
    float hf = f2tf_f(v);
    h = __float_as_uint(hf);
    l = __float_as_uint(v - hf);
}
__device__ __forceinline__ void mma_tf32(float* d,
        unsigned a0, unsigned a1, unsigned a2, unsigned a3,
        unsigned b0, unsigned b1) {
    asm("mma.sync.aligned.m16n8k8.row.col.f32.tf32.tf32.f32 "
        "{%0,%1,%2,%3}, {%4,%5,%6,%7}, {%8,%9}, {%0,%1,%2,%3};"
        : "+f"(d[0]), "+f"(d[1]), "+f"(d[2]), "+f"(d[3])
        : "r"(a0), "r"(a1), "r"(a2), "r"(a3), "r"(b0), "r"(b1));
}

// ============================================================
// Kernel 0: weight transposes
// ============================================================
__global__ void k_prep(const float* __restrict__ w2, const float* __restrict__ w3) {
    int i = blockIdx.x * blockDim.x + threadIdx.x;
    if (i < 5 * 64 * 128) {
        int k = i >> 13, oc = (i >> 7) & 63, ic = i & 127;
        g_w2T[i] = w2[oc * 640 + ic * 5 + k];
    }
    if (i < 3 * 64 * 64) {
        int k = i >> 12, oc = (i >> 6) & 63, ic = i & 63;
        g_w3T[i] = w3[oc * 192 + ic * 3 + k];
    }
}

// ============================================================
// Kernel 1: conv1 (3->128, k3) + BN + pool(3,2) + relu -> g_h1T
// ============================================================
__global__ void __launch_bounds__(128) k_conv1(
        const float* __restrict__ x,
        const float* __restrict__ w,
        const float* __restrict__ bias,
        const float* __restrict__ bng,
        const float* __restrict__ bnb,
        const float* __restrict__ bnm,
        const float* __restrict__ bnv) {
    const int b  = blockIdx.y;
    const int p0 = blockIdx.x * 64;
    const int oc = threadIdx.x;
    __shared__ float2 xs2[3][132];
    __shared__ float outS[64][128];

    const int t0 = 2 * p0;
    for (int idx = threadIdx.x; idx < 3 * 131; idx += 128) {
        int ch = idx / 131, j = idx % 131;
        int t = t0 + j;
        const float* xc = x + (b * 3 + ch) * SIGLEN;
        float v0 = (t < SIGLEN) ? xc[t] : 0.f;
        float v1 = (t + 1 < SIGLEN) ? xc[t + 1] : 0.f;
        xs2[ch][j] = make_float2(v0, v1);
    }
    ull wd[9];
#pragma unroll
    for (int j = 0; j < 9; ++j) wd[j] = dup2(w[oc * 9 + j]);
    float scale = bng[oc] / sqrtf(bnv[oc] + EPS_BN);
    float shift = bnb[oc] + (bias[oc] - bnm[oc]) * scale;
    __syncthreads();

    auto cpair = [&](int i) {
        ull a0 = 0ull, a1 = 0ull, a2 = 0ull;
#pragma unroll
        for (int k = 0; k < 3; ++k) {
            fma2(a0, wd[k],     *(const ull*)&xs2[0][2 * i + k]);
            fma2(a1, wd[3 + k], *(const ull*)&xs2[1][2 * i + k]);
            fma2(a2, wd[6 + k], *(const ull*)&xs2[2][2 * i + k]);
        }
        float lo = lo32(a0) + lo32(a1) + lo32(a2);
        float hi = hi32(a0) + hi32(a1) + hi32(a2);
        return make_float2(lo, hi);
    };

    float2 prev = cpair(0);
#pragma unroll 4
    for (int pl = 0; pl < 64; ++pl) {
        float2 nxt = cpair(pl + 1);
        float y0 = fmaf(prev.x, scale, shift);
        float y1 = fmaf(prev.y, scale, shift);
        float y2 = fmaf(nxt.x,  scale, shift);
        outS[pl][oc] = fmaxf(fmaxf(fmaxf(y0, y1), y2), 0.f);
        prev = nxt;
    }
    __syncthreads();
    for (int idx = threadIdx.x; idx < 64 * 32; idx += 128) {
        int pl = idx >> 5, q = idx & 31;
        int p = p0 + pl;
        if (p < L1P)
            *(float4*)&g_h1T[(b * L1P + p) * C1 + q * 4] =
                *(const float4*)&outS[pl][q * 4];
    }
}

// ============================================================
// Kernel 2: conv2 via mma.sync tf32 3x-split implicit GEMM  [HOT]
// R14 structure + W register-prefetch (LDG hidden under mainloop).
// ============================================================
#define CV2_SMEM ((17424 + 8448 + 128) * 4)   // 104,000 B

__global__ void __launch_bounds__(256, 2) k_conv2mma(
        const float* __restrict__ bias,
        const float* __restrict__ bng,
        const float* __restrict__ bnb,
        const float* __restrict__ bnm,
        const float* __restrict__ bnv) {
    extern __shared__ float sm[];
    float* xf  = sm;               // [132][132] f32
    float* wf  = sm + 17424;       // [64][132]  f32
    float* scS = sm + 25872;       // [64]
    float* shS = sm + 25936;       // [64]

    const int b    = blockIdx.y;
    const int bx   = blockIdx.x;
    const int ct0  = bx * 126;
    const int tid  = threadIdx.x;
    const int lane = tid & 31;
    const int wid  = tid >> 5;
    const int mw   = wid & 3;
    const int nw   = wid >> 2;

    if (tid < 64) {
        float sc = bng[tid] * rsqrtf(bnv[tid] + EPS_BN);
        scS[tid] = sc;
        shS[tid] = bnb[tid] + (bias[tid] - bnm[tid]) * sc;
    }

    const float* h1b = &g_h1T[(size_t)b * L1P * C1];
    for (int idx = tid; idx < 132 * 32; idx += 256) {
        int j = idx >> 5, icq = idx & 31;
        int t = ct0 + j;
        float* dst = xf + j * 132 + icq * 4;
        if (t < L1P) cpa16(dst, h1b + (size_t)t * C1 + icq * 4);
        else { dst[0] = 0.f; dst[1] = 0.f; dst[2] = 0.f; dst[3] = 0.f; }
    }
    // W register prefetch: 32 floats/thread (8 float4)
    float4 wr[8];
    auto ldW = [&](int k) {
#pragma unroll
        for (int i = 0; i < 8; ++i) {
            int q = tid + i * 256;          // 0..2047 quads
            wr[i] = *(const float4*)(g_w2T + k * 8192 + q * 4);
        }
    };
    auto stW = [&]() {
#pragma unroll
        for (int i = 0; i < 8; ++i) {
            int q = tid + i * 256;
            int oc = q >> 5, icq = q & 31;
            *(float4*)(wf + oc * 132 + icq * 4) = wr[i];
        }
    };
    ldW(0);
    CP_COMMIT(); CP_WAIT0();    // X fill
    stW();
    __syncthreads();

    float c[2][4][4];
#pragma unroll
    for (int ms = 0; ms < 2; ++ms)
#pragma unroll
        for (int j = 0; j < 4; ++j)
#pragma unroll
            for (int q = 0; q < 4; ++q) c[ms][j][q] = 0.f;

    for (int k = 0; k < 5; ++k) {
        if (k < 4) ldW(k + 1);
        const float* xfp = xf + (mw * 32 + (lane >> 2) + k) * 132 + (lane & 3);
        const float* wfp = wf + (nw * 32 + (lane >> 2)) * 132 + (lane & 3);
#pragma unroll 2
        for (int ks = 0; ks < 16; ++ks) {
            const int kb = ks * 8;
            unsigned ah[2][4], al[2][4], bh[4][2], bl[4][2];
#pragma unroll
            for (int ms = 0; ms < 2; ++ms) {
                int base = ms * 16 * 132 + kb;
                tfsplit(xfp[base],               ah[ms][0], al[ms][0]);
                tfsplit(xfp[base + 8 * 132],     ah[ms][1], al[ms][1]);
                tfsplit(xfp[base + 4],           ah[ms][2], al[ms][2]);
                tfsplit(xfp[base + 8 * 132 + 4], ah[ms][3], al[ms][3]);
            }
#pragma unroll
            for (int j = 0; j < 4; ++j) {
                int base = j * 8 * 132 + kb;
                tfsplit(wfp[base],     bh[j][0], bl[j][0]);
                tfsplit(wfp[base + 4], bh[j][1], bl[j][1]);
            }
#pragma unroll
            for (int ms = 0; ms < 2; ++ms)
#pragma unroll
                for (int j = 0; j < 4; ++j) {
                    mma_tf32(c[ms][j], ah[ms][0], ah[ms][1], ah[ms][2], ah[ms][3],
                             bh[j][0], bh[j][1]);
                    mma_tf32(c[ms][j], al[ms][0], al[ms][1], al[ms][2], al[ms][3],
                             bh[j][0], bh[j][1]);
                    mma_tf32(c[ms][j], ah[ms][0], ah[ms][1], ah[ms][2], ah[ms][3],
                             bl[j][0], bl[j][1]);
                }
        }
        if (k < 4) {
            __syncthreads();
            stW();
            __syncthreads();
        }
    }
    __syncthreads();

    float* convS = xf;
#pragma unroll
    for (int ms = 0; ms < 2; ++ms)
#pragma unroll
        for (int j = 0; j < 4; ++j) {
            int row = mw * 32 + ms * 16 + (lane >> 2);
            int col = nw * 32 + j * 8 + 2 * (lane & 3);
            convS[row * 68 + col]           = c[ms][j][0];
            convS[row * 68 + col + 1]       = c[ms][j][1];
            convS[(row + 8) * 68 + col]     = c[ms][j][2];
            convS[(row + 8) * 68 + col + 1] = c[ms][j][3];
        }
    __syncthreads();
    for (int idx = tid; idx < 42 * 64; idx += 256) {
        int oc = idx & 63, pl = idx >> 6;
        int p = bx * 42 + pl;
        if (p < L2P) {
            float sc = scS[oc], sh = shS[oc];
            float y0 = fmaf(convS[(3 * pl) * 68 + oc],     sc, sh);
            float y1 = fmaf(convS[(3 * pl + 1) * 68 + oc], sc, sh);
            float y2 = fmaf(convS[(3 * pl + 2) * 68 + oc], sc, sh);
            g_h2T[(b * L2P + p) * C2 + oc] = fmaxf(fmaxf(fmaxf(y0, y1), y2), 0.f);
        }
    }
}

// ============================================================
// Kernel 3: conv3 via mma.sync tf32 3x-split implicit GEMM (R14 exact)
// ============================================================
#define CV3_SMEM ((131 * 68 + 192 * 68 + 128) * 4)   // 88,368 B

__global__ void __launch_bounds__(256, 2) k_conv3mma(
        const float* __restrict__ bias,
        const float* __restrict__ bng,
        const float* __restrict__ bnb,
        const float* __restrict__ bnm,
        const float* __restrict__ bnv) {
    extern __shared__ float sm[];
    float* xf  = sm;                       // [131][68]
    float* wf  = sm + 131 * 68;            // [192][68]
    float* scS = sm + 131 * 68 + 192 * 68; // [64]
    float* shS = scS + 64;

    const int b    = blockIdx.y;
    const int bx   = blockIdx.x;
    const int ct0  = bx * 126;
    const int tid  = threadIdx.x;
    const int lane = tid & 31;
    const int wid  = tid >> 5;
    const int mw   = wid & 3;
    const int nw   = wid >> 2;

    if (tid < 64) {
        float sc = bng[tid] * rsqrtf(bnv[tid] + EPS_BN);
        scS[tid] = sc;
        shS[tid] = bnb[tid] + (bias[tid] - bnm[tid]) * sc;
    }

    for (int idx = tid; idx < 131 * 16; idx += 256) {
        int j = idx >> 4, icq = idx & 15;
        int t = ct0 + j;
        float* dst = xf + j * 68 + icq * 4;
        if (t < L2P) cpa16(dst, &g_h2T[(b * L2P + t) * C2 + icq * 4]);
        else { dst[0] = 0.f; dst[1] = 0.f; dst[2] = 0.f; dst[3] = 0.f; }
    }
    for (int idx = tid; idx < 192 * 16; idx += 256) {
        int row = idx >> 4, icq = idx & 15;
        cpa16(wf + row * 68 + icq * 4, g_w3T + row * 64 + icq * 4);
    }
    CP_COMMIT(); CP_WAIT0();
    __syncthreads();

    float c[2][4][4];
#pragma unroll
    for (int ms = 0; ms < 2; ++ms)
#pragma unroll
        for (int j = 0; j < 4; ++j)
#pragma unroll
            for (int q = 0; q < 4; ++q) c[ms][j][q] = 0.f;

#pragma unroll 1
    for (int k = 0; k < 3; ++k) {
        const float* xfp = xf + (mw * 32 + (lane >> 2) + k) * 68 + (lane & 3);
        const float* wfp = wf + (k * 64 + nw * 32 + (lane >> 2)) * 68 + (lane & 3);
#pragma unroll 2
        for (int ks = 0; ks < 8; ++ks) {
            const int kb = ks * 8;
            unsigned ah[2][4], al[2][4], bh[4][2], bl[4][2];
#pragma unroll
            for (int ms = 0; ms < 2; ++ms) {
                int base = ms * 16 * 68 + kb;
                tfsplit(xfp[base],              ah[ms][0], al[ms][0]);
                tfsplit(xfp[base + 8 * 68],     ah[ms][1], al[ms][1]);
                tfsplit(xfp[base + 4],          ah[ms][2], al[ms][2]);
                tfsplit(xfp[base + 8 * 68 + 4], ah[ms][3], al[ms][3]);
            }
#pragma unroll
            for (int j = 0; j < 4; ++j) {
                int base = j * 8 * 68 + kb;
                tfsplit(wfp[base],     bh[j][0], bl[j][0]);
                tfsplit(wfp[base + 4], bh[j][1], bl[j][1]);
            }
#pragma unroll
            for (int ms = 0; ms < 2; ++ms)
#pragma unroll
                for (int j = 0; j < 4; ++j) {
                    mma_tf32(c[ms][j], ah[ms][0], ah[ms][1], ah[ms][2], ah[ms][3],
                             bh[j][0], bh[j][1]);
                    mma_tf32(c[ms][j], al[ms][0], al[ms][1], al[ms][2], al[ms][3],
                             bh[j][0], bh[j][1]);
                    mma_tf32(c[ms][j], ah[ms][0], ah[ms][1], ah[ms][2], ah[ms][3],
                             bl[j][0], bl[j][1]);
                }
        }
    }
    __syncthreads();

    float* convS = xf;   // [128][68]
#pragma unroll
    for (int ms = 0; ms < 2; ++ms)
#pragma unroll
        for (int j = 0; j < 4; ++j) {
            int row = mw * 32 + ms * 16 + (lane >> 2);
            int col = nw * 32 + j * 8 + 2 * (lane & 3);
            convS[row * 68 + col]           = c[ms][j][0];
            convS[row * 68 + col + 1]       = c[ms][j][1];
            convS[(row + 8) * 68 + col]     = c[ms][j][2];
            convS[(row + 8) * 68 + col + 1] = c[ms][j][3];
        }
    __syncthreads();
    for (int idx = tid; idx < 63 * 64; idx += 256) {
        int oc = idx & 63, pl = idx >> 6;
        int p = bx * 63 + pl;
        if (p < L3P) {
            float sc = scS[oc], sh = shS[oc];
            float y0 = fmaf(convS[(2 * pl) * 68 + oc],     sc, sh);
            float y1 = fmaf(convS[(2 * pl + 1) * 68 + oc], sc, sh);
            float y2 = fmaf(convS[(2 * pl + 2) * 68 + oc], sc, sh);
            float y = fmaxf(fmaxf(fmaxf(y0, y1), y2), 0.f);
            g_h3T[(oc * L3P + p) * BATCH + b] = y;
        }
    }
}

// ============================================================
// Kernel 4a: fc1 split-K, x-slab staged in smem.
// ============================================================
#define FCA_SMEM ((2016 + 10752) * 4)   // 51,072 B

__global__ void __launch_bounds__(256) k_fcA(const float* __restrict__ fc1w) {
    extern __shared__ float sm[];
    float* wsS = sm;           // [42][48]
    float* xS  = sm + 2016;    // [42][256]

    const int chunk = blockIdx.x;
    const int r = threadIdx.x;

    for (int idx = r; idx < 42 * 48; idx += 256) {
        int o = idx / 42, k = idx % 42;
        wsS[k * 48 + o] = fc1w[o * FCIN + chunk * 42 + k];
    }
    for (int i = r * 4; i < 10752; i += 1024)
        cpa16(xS + i, g_h3T + (size_t)chunk * 10752 + i);
    CP_COMMIT(); CP_WAIT0();
    __syncthreads();

    ull acc[24];
#pragma unroll
    for (int p = 0; p < 24; ++p) acc[p] = 0ull;

#pragma unroll 2
    for (int k = 0; k < 42; ++k) {
        ull xd = dup2(xS[k * 256 + r]);
#pragma unroll
        for (int p = 0; p < 24; ++p)
            fma2(acc[p], *(const ull*)&wsS[k * 48 + 2 * p], xd);
    }
    float* outp = &g_part[(chunk * BATCH + r) * 48];
#pragma unroll
    for (int p = 0; p < 24; ++p) {
        outp[2 * p]     = lo32(acc[p]);
        outp[2 * p + 1] = hi32(acc[p]);
    }
}

// ============================================================
// Kernel 4b: reduce (parallelized) + fc2/fc3/fc4 + tanh
// ============================================================
__global__ void __launch_bounds__(256) k_fcB(
        const float* __restrict__ fc1b,
        const float* __restrict__ fc2w, const float* __restrict__ fc2b,
        const float* __restrict__ fc3w, const float* __restrict__ fc3b,
        const float* __restrict__ fc4w, const float* __restrict__ fc4b) {
    const int r = blockIdx.x;
    const int tid = threadIdx.x;
    const int t = tid % 48, g = tid / 48;
    __shared__ float part[5][48];
    __shared__ float s1[48], s2[32], s3[16];

    if (g < 5) {
        int c0 = g * 52;
        int c1 = (c0 + 52 < 256) ? c0 + 52 : 256;
        float a = 0.f;
        for (int c = c0; c < c1; ++c)
            a += g_part[(c * BATCH + r) * 48 + t];
        part[g][t] = a;
    }
    __syncthreads();
    if (tid < 48) {
        float a = part[0][tid] + part[1][tid] + part[2][tid]
                + part[3][tid] + part[4][tid];
        s1[tid] = fmaxf(a + fc1b[tid], 0.f);
    }
    __syncthreads();
    if (tid < 32) {
        float a2 = 0.f;
#pragma unroll
        for (int k = 0; k < 48; ++k) a2 = fmaf(s1[k], fc2w[tid * 48 + k], a2);
        s2[tid] = fmaxf(a2 + fc2b[tid], 0.f);
    }
    __syncthreads();
    if (tid < 16) {
        float a3 = 0.f;
#pragma unroll
        for (int k = 0; k < 32; ++k) a3 = fmaf(s2[k], fc3w[tid * 32 + k], a3);
        s3[tid] = fmaxf(a3 + fc3b[tid], 0.f);
    }
    __syncthreads();
    if (tid < 5) {
        float a4 = 0.f;
#pragma unroll
        for (int k = 0; k < 16; ++k) a4 = fmaf(s3[k], fc4w[tid * 16 + k], a4);
        g_theta[r * 5 + tid] = tanhf(a4 + fc4b[tid]);
    }
}

// ============================================================
// Kernel 5: CPAB integrate + resample
// ============================================================
__global__ void k_warp(const float* __restrict__ x,
                       const float* __restrict__ basis,
                       float* __restrict__ out) {
    const int b   = blockIdx.x;
    const int tid = threadIdx.x;
    __shared__ float sa[6], sb[6];
    if (tid < 12) {
        float a = 0.f;
#pragma unroll
        for (int k = 0; k < 5; ++k)
            a = fmaf(g_theta[b * 5 + k], basis[tid * 5 + k], a);
        if (tid & 1) sb[tid >> 1] = a; else sa[tid >> 1] = a;
    }
    __syncthreads();
    float la[6], lb[6];
#pragma unroll
    for (int c = 0; c < 6; ++c) { la[c] = sa[c]; lb[c] = sb[c]; }
    const float INF = __int_as_float(0x7f800000);

    for (int r = 0; r < 8; ++r) {
        int i = tid + r * 256;
        float xv = (float)i / 2047.0f;
        float t = 1.0f;
#pragma unroll 1
        for (int it = 0; it < 7; ++it) {
            int c = (int)floorf(xv * 6.0f);
            c = c < 0 ? 0 : (c > 5 ? 5 : c);
            float a  = la[c];
            float bc = lb[c];
            float v  = fmaf(a, xv, bc);
            float xb = (v >= 0.f) ? (float)(c + 1) / 6.0f : (float)c / 6.0f;
            bool  big = fabsf(a) > 1e-8f;
            float a_s = big ? a : 1.0f;
            float boa = bc / a_s;
            float z   = xv + boa;
            float zb  = xb + boa;
            float zden  = (fabsf(z) > 1e-12f) ? z : 1e-12f;
            float ratio = zb / zden;
            float t_exp = logf(fmaxf(ratio, 1e-12f)) / a_s;
            float v_s   = (fabsf(v) > 1e-12f) ? v : 1.0f;
            float t_lin = (xb - xv) / v_s;
            float thit  = big ? t_exp : t_lin;
            bool valid = (fabsf(v) > 1e-12f) && (thit > 0.f) &&
                         ((big ? ratio : 1.0f) > 0.f);
            thit = valid ? thit : INF;
            float tau = fminf(t, thit);
            float x_new = big ? (z * expf(a * tau) - (z - xv))
                              : fmaf(bc, tau, xv);
            bool hit = (thit <= t);
            float nudge = (v >= 0.f) ? 1e-6f : -1e-6f;
            xv = hit ? (xb + nudge) : x_new;
            xv = fminf(fmaxf(xv, 0.f), 1.f);
            t = fmaxf(t - tau, 0.f);
        }
        float p = fminf(fmaxf(xv, 0.f), 1.f) * 2047.0f;
        int x0 = (int)floorf(p);
        x0 = x0 < 0 ? 0 : (x0 > 2046 ? 2046 : x0);
        float wgt = p - (float)x0;
#pragma unroll
        for (int ch = 0; ch < 3; ++ch) {
            float d0 = x[(b * 3 + ch) * SIGLEN + x0];
            float d1 = x[(b * 3 + ch) * SIGLEN + x0 + 1];
            out[(b * 3 + ch) * SIGLEN + i] = d0 * (1.0f - wgt) + d1 * wgt;
        }
    }
}

// ============================================================
extern "C" void kernel_launch(void* const* d_in, const int* in_sizes, int n_in,
                              void* d_out, int out_size) {
    const float* x     = (const float*)d_in[0];
    const float* c1w   = (const float*)d_in[1];
    const float* c1b   = (const float*)d_in[2];
    const float* bn1g  = (const float*)d_in[3];
    const float* bn1b  = (const float*)d_in[4];
    const float* bn1m  = (const float*)d_in[5];
    const float* bn1v  = (const float*)d_in[6];
    const float* c2w   = (const float*)d_in[7];
    const float* c2b   = (const float*)d_in[8];
    const float* bn2g  = (const float*)d_in[9];
    const float* bn2b  = (const float*)d_in[10];
    const float* bn2m  = (const float*)d_in[11];
    const float* bn2v  = (const float*)d_in[12];
    const float* c3w   = (const float*)d_in[13];
    const float* c3b   = (const float*)d_in[14];
    const float* bn3g  = (const float*)d_in[15];
    const float* bn3b  = (const float*)d_in[16];
    const float* bn3m  = (const float*)d_in[17];
    const float* bn3v  = (const float*)d_in[18];
    const float* fc1w  = (const float*)d_in[19];
    const float* fc1b  = (const float*)d_in[20];
    const float* fc2w  = (const float*)d_in[21];
    const float* fc2b  = (const float*)d_in[22];
    const float* fc3w  = (const float*)d_in[23];
    const float* fc3b  = (const float*)d_in[24];
    const float* fc4w  = (const float*)d_in[25];
    const float* fc4b  = (const float*)d_in[26];
    const float* basis = (const float*)d_in[27];
    float* out = (float*)d_out;

    static int attr_done = 0;
    if (!attr_done) {
        cudaFuncSetAttribute(k_conv2mma,
                             cudaFuncAttributeMaxDynamicSharedMemorySize, CV2_SMEM);
        cudaFuncSetAttribute(k_conv3mma,
                             cudaFuncAttributeMaxDynamicSharedMemorySize, CV3_SMEM);
        cudaFuncSetAttribute(k_fcA,
                             cudaFuncAttributeMaxDynamicSharedMemorySize, FCA_SMEM);
        attr_done = 1;
    }

    k_prep<<<160, 256>>>(c2w, c3w);
    dim3 g1(16, BATCH);  k_conv1<<<g1, 128>>>(x, c1w, c1b, bn1g, bn1b, bn1m, bn1v);
    dim3 g2(9,  BATCH);  k_conv2mma<<<g2, 256, CV2_SMEM>>>(c2b, bn2g, bn2b, bn2m, bn2v);
    dim3 g3(3,  BATCH);  k_conv3mma<<<g3, 256, CV3_SMEM>>>(c3b, bn3g, bn3b, bn3m, bn3v);
    k_fcA<<<256, 256, FCA_SMEM>>>(fc1w);
    k_fcB<<<BATCH, 256>>>(fc1b, fc2w, fc2b, fc3w, fc3b, fc4w, fc4b);
    k_warp<<<BATCH, 256>>>(x, basis, out);
}